// round 2
// baseline (speedup 1.0000x reference)
#include <cuda_runtime.h>
#include <cstdint>

// Problem constants (from reference): x[M,4096] fp32, qweight[4096,1376] int32
// (8 int4 nibbles per int32 along OUT dim), qzeros[32,1376] int32,
// scales[32,11008] fp32, bias[11008] fp32. out[M,11008] fp32.
// W[k][n] = (nib(qweight[k][n/8], n%8) - nib(qzeros[k/128][n/8], n%8)) * scales[k/128][n]

#define KDIM    4096
#define NDIM    11008
#define NPACK   1376      // NDIM/8
#define BM      128
#define BN      128
#define BK      32
#define APAD    4         // As stride 36: frag bank = (4m+c)%32 -> conflict-free
#define BPAD    8         // Bs stride 136: frag bank = (8k+n)%32 -> conflict-free

__device__ __forceinline__ float to_tf32(float x) {
    uint32_t u;
    asm("cvt.rna.tf32.f32 %0, %1;" : "=r"(u) : "f"(x));
    return __uint_as_float(u);
}

__device__ __forceinline__ void mma_tf32(float* d, const uint32_t* a, const uint32_t* b) {
    asm volatile(
        "mma.sync.aligned.m16n8k8.row.col.f32.tf32.tf32.f32 "
        "{%0,%1,%2,%3}, {%4,%5,%6,%7}, {%8,%9}, {%0,%1,%2,%3};"
        : "+f"(d[0]), "+f"(d[1]), "+f"(d[2]), "+f"(d[3])
        : "r"(a[0]), "r"(a[1]), "r"(a[2]), "r"(a[3]), "r"(b[0]), "r"(b[1]));
}

__global__ __launch_bounds__(256) void qlin_tf32_kernel(
    const float* __restrict__ x,
    const int*   __restrict__ qweight,
    const int*   __restrict__ qzeros,
    const float* __restrict__ scales,
    const float* __restrict__ bias,
    float*       __restrict__ out,
    int M)
{
    __shared__ float As[BM][BK + APAD];   // A[m][k]
    __shared__ float Bs[BK][BN + BPAD];   // W[k][n], dequantized tf32

    const int tid  = threadIdx.x;
    const int lane = tid & 31;
    const int wid  = tid >> 5;            // 8 warps
    const int wm   = wid >> 1;            // 0..3 -> 32-row slice
    const int wn   = wid & 1;             // 0..1 -> 64-col slice

    const int m0 = blockIdx.y * BM;
    const int n0 = blockIdx.x * BN;

    float acc[2][8][4];
    #pragma unroll
    for (int im = 0; im < 2; im++)
        #pragma unroll
        for (int in = 0; in < 8; in++)
            #pragma unroll
            for (int r = 0; r < 4; r++) acc[im][in][r] = 0.0f;

    // ---- per-thread load coordinates ----
    // A: 128 rows x 32 k-floats; 256 threads x 4 passes of float4
    const int aRow = tid >> 3;            // 0..31 (+32 per pass)
    const int aCol = (tid & 7) * 4;       // 0,4,...,28
    // B: 32 k-rows x 16 packed int32; 256 threads handle idx=tid and tid+256
    const int bK    = tid >> 4;           // 0..15 (second item: +16)
    const int bPack = tid & 15;           // packed-column within tile

    float4 aReg[4];
    int    qReg[2];
    int    zReg;
    float  sReg[8];

    auto load_tile = [&](int k0) {
        #pragma unroll
        for (int p = 0; p < 4; p++) {
            int row = p * 32 + aRow;
            if (m0 + row < M)
                aReg[p] = *reinterpret_cast<const float4*>(
                    &x[(m0 + row) * KDIM + k0 + aCol]);
            else
                aReg[p] = make_float4(0.f, 0.f, 0.f, 0.f);
        }
        const int g     = k0 >> 7;                 // group (BK=32 never crosses)
        const int nblk  = (n0 >> 3) + bPack;       // packed column index
        qReg[0] = qweight[(k0 + bK) * NPACK + nblk];
        qReg[1] = qweight[(k0 + bK + 16) * NPACK + nblk];
        zReg    = qzeros[g * NPACK + nblk];
        #pragma unroll
        for (int j = 0; j < 8; j++)
            sReg[j] = scales[g * NDIM + n0 + bPack * 8 + j];
    };

    auto store_tile = [&]() {
        #pragma unroll
        for (int p = 0; p < 4; p++) {
            int row = p * 32 + aRow;
            As[row][aCol + 0] = to_tf32(aReg[p].x);
            As[row][aCol + 1] = to_tf32(aReg[p].y);
            As[row][aCol + 2] = to_tf32(aReg[p].z);
            As[row][aCol + 3] = to_tf32(aReg[p].w);
        }
        #pragma unroll
        for (int r = 0; r < 2; r++) {
            const int k = bK + r * 16;
            const int q = qReg[r];
            #pragma unroll
            for (int j = 0; j < 8; j++) {
                float w = (float)((q >> (4 * j)) & 0xF)
                        - (float)((zReg >> (4 * j)) & 0xF);
                Bs[k][bPack * 8 + j] = to_tf32(w * sReg[j]);
            }
        }
    };

    auto compute = [&]() {
        const int fr = lane >> 2;   // 0..7
        const int fc = lane & 3;    // 0..3
        #pragma unroll
        for (int ks = 0; ks < 4; ks++) {
            const int kk = ks * 8;
            uint32_t a[2][4], b[8][2];
            #pragma unroll
            for (int im = 0; im < 2; im++) {
                const int mb = wm * 32 + im * 16;
                a[im][0] = __float_as_uint(As[mb + fr    ][kk + fc    ]);
                a[im][1] = __float_as_uint(As[mb + fr + 8][kk + fc    ]);
                a[im][2] = __float_as_uint(As[mb + fr    ][kk + fc + 4]);
                a[im][3] = __float_as_uint(As[mb + fr + 8][kk + fc + 4]);
            }
            #pragma unroll
            for (int in = 0; in < 8; in++) {
                const int nb = wn * 64 + in * 8;
                b[in][0] = __float_as_uint(Bs[kk + fc    ][nb + fr]);
                b[in][1] = __float_as_uint(Bs[kk + fc + 4][nb + fr]);
            }
            #pragma unroll
            for (int im = 0; im < 2; im++)
                #pragma unroll
                for (int in = 0; in < 8; in++)
                    mma_tf32(acc[im][in], a[im], b[in]);
        }
    };

    // ---- main loop: register-prefetch next tile while computing current ----
    const int ntiles = KDIM / BK;   // 128
    load_tile(0);
    store_tile();
    __syncthreads();

    for (int t = 0; t < ntiles; t++) {
        if (t + 1 < ntiles) load_tile((t + 1) * BK);   // global loads in flight
        compute();                                      // MMA on smem tile t
        __syncthreads();
        if (t + 1 < ntiles) {
            store_tile();
            __syncthreads();
        }
    }

    // ---- epilogue: bias + store fp32 ----
    const int fr = lane >> 2;
    const int fc = lane & 3;
    #pragma unroll
    for (int im = 0; im < 2; im++) {
        #pragma unroll
        for (int in = 0; in < 8; in++) {
            const int row = m0 + wm * 32 + im * 16 + fr;
            const int col = n0 + wn * 64 + in * 8 + fc * 2;
            const float b0 = bias[col];
            const float b1 = bias[col + 1];
            if (row < M) {
                float2 v = make_float2(acc[im][in][0] + b0, acc[im][in][1] + b1);
                *reinterpret_cast<float2*>(&out[(size_t)row * NDIM + col]) = v;
            }
            if (row + 8 < M) {
                float2 v = make_float2(acc[im][in][2] + b0, acc[im][in][3] + b1);
                *reinterpret_cast<float2*>(&out[(size_t)(row + 8) * NDIM + col]) = v;
            }
        }
    }
}

extern "C" void kernel_launch(void* const* d_in, const int* in_sizes, int n_in,
                              void* d_out, int out_size)
{
    const float* x    = (const float*)d_in[0];
    const int*   qw   = (const int*)  d_in[1];
    const int*   qz   = (const int*)  d_in[2];
    const float* sc   = (const float*)d_in[3];
    const float* bias = (const float*)d_in[4];
    float*       out  = (float*)d_out;

    const int M = in_sizes[0] / KDIM;   // 2048 for this problem

    dim3 grid(NDIM / BN, (M + BM - 1) / BM);   // (86, 16)
    qlin_tf32_kernel<<<grid, 256>>>(x, qw, qz, sc, bias, out, M);
}

// round 4
// speedup vs baseline: 2.5967x; 2.5967x over previous
#include <cuda_runtime.h>
#include <cuda_fp16.h>
#include <cstdint>

// out[M,11008] = x[M,4096] @ dequant(qweight) + bias
// W[k][n] = (nib(qw[k][n/8],n%8) - nib(qz[k/128][n/8],n%8)) * sc[k/128][n]
// Toolchain constraint: PTX target is compute_103 (no 'a') -> no tcgen05.
// Path: fp16 mma.sync.m16n8k16 + ldmatrix + cp.async, fp16-x prepass.

#define KDIM    4096
#define NDIM    11008
#define NPACK   1376
#define BM      128
#define BN      128
#define BK      64
#define NCHUNK  64              // KDIM/BK
#define MAXM    2048
#define A_STAGE 16384           // 128 rows x 64 fp16 (128B rows, SW128)
#define B_STAGE 16384           // 2 subtiles of [64k][64n] fp16 (8KB each, SW128)
#define SMEM_DYN (3*A_STAGE + 2*B_STAGE + 1024)   // 3-stage A, 2-stage B

__device__ __half x16g[(size_t)MAXM * KDIM];      // fp16 copy of x (prepass output)

__device__ __forceinline__ uint32_t smem_u32(const void* p) {
    uint32_t a;
    asm("{ .reg .u64 t; cvta.to.shared.u64 t, %1; cvt.u32.u64 %0, t; }" : "=r"(a) : "l"(p));
    return a;
}
__device__ __forceinline__ uint32_t sw128(uint32_t o) { return o ^ ((o >> 3) & 0x70); }

#define LDSM_X4(r0,r1,r2,r3,addr) \
    asm volatile("ldmatrix.sync.aligned.m8n8.x4.shared.b16 {%0,%1,%2,%3}, [%4];" \
        : "=r"(r0),"=r"(r1),"=r"(r2),"=r"(r3) : "r"(addr))
#define LDSM_X4_T(r0,r1,r2,r3,addr) \
    asm volatile("ldmatrix.sync.aligned.m8n8.x4.trans.shared.b16 {%0,%1,%2,%3}, [%4];" \
        : "=r"(r0),"=r"(r1),"=r"(r2),"=r"(r3) : "r"(addr))

__device__ __forceinline__ void mma16816(float* d, const uint32_t* a,
                                         uint32_t b0, uint32_t b1) {
    asm volatile(
        "mma.sync.aligned.m16n8k16.row.col.f32.f16.f16.f32 "
        "{%0,%1,%2,%3}, {%4,%5,%6,%7}, {%8,%9}, {%0,%1,%2,%3};"
        : "+f"(d[0]), "+f"(d[1]), "+f"(d[2]), "+f"(d[3])
        : "r"(a[0]), "r"(a[1]), "r"(a[2]), "r"(a[3]), "r"(b0), "r"(b1));
}
__device__ __forceinline__ void cp16(uint32_t saddr, const void* g) {
    asm volatile("cp.async.cg.shared.global [%0], [%1], 16;" :: "r"(saddr), "l"(g));
}

// ---------------- prepass: x fp32 -> fp16 (rows >= M zero-filled) ----------------
__global__ __launch_bounds__(256) void cvt_x(const float* __restrict__ x, int M) {
    const size_t i = (size_t)blockIdx.x * 256 + threadIdx.x;   // 8-elem chunk id
    const size_t e = i * 8;
    if (e >= (size_t)MAXM * KDIM) return;
    const int row = (int)(e >> 12);
    uint4 v;
    if (row < M) {
        const float4 f0 = reinterpret_cast<const float4*>(x + e)[0];
        const float4 f1 = reinterpret_cast<const float4*>(x + e)[1];
        __half2 p0 = __floats2half2_rn(f0.x, f0.y);
        __half2 p1 = __floats2half2_rn(f0.z, f0.w);
        __half2 p2 = __floats2half2_rn(f1.x, f1.y);
        __half2 p3 = __floats2half2_rn(f1.z, f1.w);
        v.x = *reinterpret_cast<uint32_t*>(&p0);
        v.y = *reinterpret_cast<uint32_t*>(&p1);
        v.z = *reinterpret_cast<uint32_t*>(&p2);
        v.w = *reinterpret_cast<uint32_t*>(&p3);
    } else {
        v = make_uint4(0, 0, 0, 0);
    }
    *reinterpret_cast<uint4*>(x16g + e) = v;
}

// ---------------- main GEMM ----------------
__global__ __launch_bounds__(256, 2) void qlin_f16(
    const int*   __restrict__ qw,
    const int*   __restrict__ qz,
    const float* __restrict__ sc,
    const float* __restrict__ bias,
    float*       __restrict__ out,
    int M)
{
    extern __shared__ char smem_raw[];
    const uint32_t sb = (smem_u32(smem_raw) + 1023) & ~1023u;
    const uint32_t sA[3] = { sb, sb + A_STAGE, sb + 2 * A_STAGE };
    const uint32_t sB[2] = { sb + 3 * A_STAGE, sb + 3 * A_STAGE + B_STAGE };

    const int tid  = threadIdx.x;
    const int lane = tid & 31;
    const int wid  = tid >> 5;
    const int wm   = wid >> 1;          // 0..3
    const int wn   = wid & 1;           // 0..1
    const int m0   = blockIdx.y * BM;
    const int n0   = blockIdx.x * BN;

    float acc[2][8][4];
    #pragma unroll
    for (int im = 0; im < 2; im++)
        #pragma unroll
        for (int jn = 0; jn < 8; jn++)
            #pragma unroll
            for (int r = 0; r < 4; r++) acc[im][jn][r] = 0.f;

    // ---- A cp.async coords: 1024 16B chunks, 4 per thread ----
    // chunk c: row = c>>3 (0..127), kc = c&7 (16B = 8 halves)
    auto cpA = [&](int t, int stg) {
        const __half* src = x16g + (size_t)(m0) * KDIM + t * BK;
        #pragma unroll
        for (int p = 0; p < 4; p++) {
            const int c   = tid + p * 256;
            const int row = c >> 3, kc = c & 7;
            cp16(sA[stg] + sw128((uint32_t)(row * 128 + kc * 16)),
                 src + (size_t)row * KDIM + kc * 8);
        }
        asm volatile("cp.async.commit_group;");
    };

    // ---- B dequant coords ----
    const int nb = tid & 15;            // packed col (8 n each) within BN=128
    const int kq = tid >> 4;            // 0..15
    const size_t nbG = (size_t)(n0 >> 3) + nb;
    __half2 zc[4], s2[4];
    int qreg[4];

    auto refresh_group = [&](int g) {
        const uint32_t zq = (uint32_t)qz[(size_t)g * NPACK + nbG];
        #pragma unroll
        for (int j = 0; j < 4; j++) {
            uint32_t p = ((zq >> (4 * j)) & 0x000F000Fu) | 0x64006400u;
            zc[j] = *reinterpret_cast<__half2*>(&p);
        }
        const float4* sp = reinterpret_cast<const float4*>(
            sc + (size_t)g * NDIM + n0 + nb * 8);
        const float4 sa = sp[0], sbv = sp[1];
        s2[0] = __floats2half2_rn(sa.x, sbv.x);
        s2[1] = __floats2half2_rn(sa.y, sbv.y);
        s2[2] = __floats2half2_rn(sa.z, sbv.z);
        s2[3] = __floats2half2_rn(sa.w, sbv.w);
    };
    auto ldgQ = [&](int t) {
        #pragma unroll
        for (int i = 0; i < 4; i++)
            qreg[i] = qw[(size_t)(t * BK + kq + 16 * i) * NPACK + nbG];
    };
    auto dequantB = [&](int stg) {
        char* Bsub = smem_raw + (sB[stg] - smem_u32(smem_raw)) + (nb >> 3) * 8192;
        const uint32_t cb = (uint32_t)((nb & 7) * 16);
        #pragma unroll
        for (int i = 0; i < 4; i++) {
            const int k = kq + 16 * i;
            const uint32_t q = (uint32_t)qreg[i];
            uint32_t w[4];
            #pragma unroll
            for (int j = 0; j < 4; j++) {
                uint32_t p = ((q >> (4 * j)) & 0x000F000Fu) | 0x64006400u;
                __half2 hv = __hmul2(__hsub2(*reinterpret_cast<__half2*>(&p), zc[j]), s2[j]);
                w[j] = *reinterpret_cast<uint32_t*>(&hv);
            }
            uint4 v;   // pair reorder -> n0..n7 memory order
            v.x = __byte_perm(w[0], w[1], 0x5410);
            v.y = __byte_perm(w[2], w[3], 0x5410);
            v.z = __byte_perm(w[0], w[1], 0x7632);
            v.w = __byte_perm(w[2], w[3], 0x7632);
            *reinterpret_cast<uint4*>(Bsub + sw128((uint32_t)(k * 128) + cb)) = v;
        }
    };

    // ---- compute one BK=64 chunk from smem ----
    const int lr = lane & 15, lc = lane >> 4;
    auto compute = [&](int aStg, int bStg) {
        const uint32_t aB = sA[aStg];
        const uint32_t bB = sB[bStg] + wn * 8192;
        #pragma unroll
        for (int ks = 0; ks < 4; ks++) {
            uint32_t a[2][4];
            #pragma unroll
            for (int im = 0; im < 2; im++) {
                const uint32_t addr = aB + sw128(
                    (uint32_t)((wm * 32 + im * 16 + lr) * 128 + ks * 32 + lc * 16));
                LDSM_X4(a[im][0], a[im][1], a[im][2], a[im][3], addr);
            }
            #pragma unroll
            for (int jn = 0; jn < 4; jn++) {
                uint32_t b0, b1, b2, b3;
                const uint32_t addr = bB + sw128(
                    (uint32_t)((ks * 16 + lr) * 128 + jn * 32 + lc * 16));
                LDSM_X4_T(b0, b1, b2, b3, addr);
                #pragma unroll
                for (int im = 0; im < 2; im++) {
                    mma16816(acc[im][2 * jn],     a[im], b0, b1);
                    mma16816(acc[im][2 * jn + 1], a[im], b2, b3);
                }
            }
        }
    };

    // ---- prologue ----
    ldgQ(0);
    cpA(0, 0);
    cpA(1, 1);
    refresh_group(0);
    dequantB(0);                       // Bs[0] = chunk 0
    ldgQ(1);
    asm volatile("cp.async.wait_group 1;");   // A0 ready
    __syncthreads();

    // ---- main loop ----
    for (int t = 0; t < NCHUNK; t++) {
        compute(t % 3, t & 1);
        if (t + 2 < NCHUNK) cpA(t + 2, (t + 2) % 3);
        if (t + 1 < NCHUNK) {
            if (((t + 1) & 1) == 0) refresh_group((t + 1) >> 1);
            dequantB((t + 1) & 1);
            if (t + 2 < NCHUNK) ldgQ(t + 2);
            asm volatile("cp.async.wait_group 1;");   // A(t+1) ready
            __syncthreads();
        }
    }

    // ---- epilogue ----
    #pragma unroll
    for (int im = 0; im < 2; im++) {
        const int row = m0 + wm * 32 + im * 16 + (lane >> 2);
        #pragma unroll
        for (int jn = 0; jn < 8; jn++) {
            const int col = n0 + wn * 64 + jn * 8 + (lane & 3) * 2;
            const float b0 = bias[col], b1 = bias[col + 1];
            const float* c = acc[im][jn];
            if (row < M)
                *reinterpret_cast<float2*>(out + (size_t)row * NDIM + col) =
                    make_float2(c[0] + b0, c[1] + b1);
            if (row + 8 < M)
                *reinterpret_cast<float2*>(out + (size_t)(row + 8) * NDIM + col) =
                    make_float2(c[2] + b0, c[3] + b1);
        }
    }
}

extern "C" void kernel_launch(void* const* d_in, const int* in_sizes, int n_in,
                              void* d_out, int out_size)
{
    const float* x    = (const float*)d_in[0];
    const int*   qw   = (const int*)  d_in[1];
    const int*   qz   = (const int*)  d_in[2];
    const float* sc   = (const float*)d_in[3];
    const float* bias = (const float*)d_in[4];
    float*       out  = (float*)d_out;

    int M = in_sizes[0] / KDIM;
    if (M > MAXM) M = MAXM;

    cvt_x<<<(MAXM * KDIM / 8 + 255) / 256, 256>>>(x, M);

    cudaFuncSetAttribute(qlin_f16, cudaFuncAttributeMaxDynamicSharedMemorySize, SMEM_DYN);
    dim3 grid(NDIM / BN, (M + BM - 1) / BM);   // (86, 16)
    qlin_f16<<<grid, 256, SMEM_DYN>>>(qw, qz, sc, bias, out, M);
}